// round 10
// baseline (speedup 1.0000x reference)
#include <cuda_runtime.h>
#include <cuda_bf16.h>
#include <math.h>
#include <stdint.h>

#define N_VARS 50000
#define HID 128
#define N_EDGES 400000
#define NP 50048            // 391 * 128
#define NBLK (NP / 128)     // 391
#define STEPS 4
#define BN_EPS 1e-5f

// ---------------- static device scratch ----------------
// GEMM operands in GMEM in TILED-SWIZZLED layout:
//   tile = 128 rows x 64 k bf16 = 16KB; byte off in tile = SWZ(row*128 + kbyte)
__device__ float g_hA[NP * HID];
__device__ float g_hB[NP * HID];
__device__ float g_c[NP * HID];
__device__ float g_degf[NP];
__device__ int   g_degi[NP];
__device__ int   g_off[NP + 1];
__device__ int   g_cur[NP];
__device__ int   g_adj[2 * N_EDGES];
__device__ __align__(16) __nv_bfloat16 g_W1h[4 * 8192];     // 4 K-chunk tiles
__device__ __align__(16) __nv_bfloat16 g_W1l[4 * 8192];
__device__ __align__(16) __nv_bfloat16 g_W2h[16 * 8192];    // 16 tiles (4 nBlk x 4 chunk)
__device__ __align__(16) __nv_bfloat16 g_W2l[16 * 8192];
__device__ float g_W2f[512 * 256];                          // permuted fp32 master
__device__ __align__(16) __nv_bfloat16 g_X1h[NBLK * 4 * 8192];   // [agg | deg*h]
__device__ __align__(16) __nv_bfloat16 g_X1l[NBLK * 4 * 8192];
__device__ __align__(16) __nv_bfloat16 g_XRh[NBLK * 2 * 8192];   // split(rec) (k<128)
__device__ __align__(16) __nv_bfloat16 g_XRl[NBLK * 2 * 8192];
__device__ __align__(16) __nv_bfloat16 g_XHh[2][NBLK * 2 * 8192];// split(h) ping-pong
__device__ __align__(16) __nv_bfloat16 g_XHl[2][NBLK * 2 * 8192];
__device__ float g_bias[4 * HID];
__device__ __align__(16) float g_bias2[512];                // per-step folded bias
__device__ float g_stats[2 * HID];

__device__ __forceinline__ float sigf(float x) { return 1.0f / (1.0f + expf(-x)); }

__device__ __forceinline__ uint32_t smem_u32(const void* p) {
    uint32_t a;
    asm("{ .reg .u64 t; cvta.to.shared.u64 t, %1; cvt.u32.u64 %0, t; }" : "=r"(a) : "l"(p));
    return a;
}
#define SWZ(o) ((o) ^ (((o) >> 3) & 0x70))

__device__ __forceinline__ size_t tsw(int tile, int row, int kbyte) {
    return (size_t)tile * 16384 + (uint32_t)SWZ((uint32_t)(row * 128 + kbyte));
}

#define LDSM4(R, A) \
    asm volatile("ldmatrix.sync.aligned.m8n8.x4.shared.b16 {%0,%1,%2,%3}, [%4];" \
                 : "=r"((R)[0]), "=r"((R)[1]), "=r"((R)[2]), "=r"((R)[3]) : "r"(A))

#define MMA(C, A, B0, B1) \
    asm volatile("mma.sync.aligned.m16n8k16.row.col.f32.bf16.bf16.f32 " \
                 "{%0,%1,%2,%3},{%4,%5,%6,%7},{%8,%9},{%0,%1,%2,%3};" \
                 : "+f"((C)[0]), "+f"((C)[1]), "+f"((C)[2]), "+f"((C)[3]) \
                 : "r"((A)[0]), "r"((A)[1]), "r"((A)[2]), "r"((A)[3]), "r"(B0), "r"(B1))

#define MBAR_INIT(a, c) \
    asm volatile("mbarrier.init.shared.b64 [%0], %1;" :: "r"(a), "r"(c) : "memory")
#define MBAR_EXPECT(a, b) \
    asm volatile("mbarrier.arrive.expect_tx.shared.b64 _, [%0], %1;" :: "r"(a), "r"(b) : "memory")

__device__ __forceinline__ void mbar_wait(uint32_t mbar, uint32_t parity) {
    asm volatile(
        "{\n\t.reg .pred P;\n\t"
        "WLOOP_%=:\n\t"
        "mbarrier.try_wait.parity.shared.b64 P, [%0], %1;\n\t"
        "@P bra.uni WDONE_%=;\n\t"
        "bra.uni WLOOP_%=;\n\t"
        "WDONE_%=:\n\t}"
        :: "r"(mbar), "r"(parity) : "memory");
}

__device__ __forceinline__ void bulk_cp(uint32_t dst, const void* src, uint32_t bytes,
                                        uint32_t mbar) {
    asm volatile(
        "cp.async.bulk.shared::cluster.global.mbarrier::complete_tx::bytes [%0], [%1], %2, [%3];"
        :: "r"(dst), "l"(src), "r"(bytes), "r"(mbar) : "memory");
}

union Pack8 { __nv_bfloat16 b[8]; uint4 u; };
__device__ __forceinline__ void split8(float4 a, float4 b, uint4& hi, uint4& lo) {
    float v[8] = {a.x, a.y, a.z, a.w, b.x, b.y, b.z, b.w};
    Pack8 ph, pl;
#pragma unroll
    for (int i = 0; i < 8; i++) {
        __nv_bfloat16 h = __float2bfloat16(v[i]);
        ph.b[i] = h;
        pl.b[i] = __float2bfloat16(v[i] - __bfloat162float(h));
    }
    hi = ph.u; lo = pl.u;
}
union Pack4 { __nv_bfloat16 b[4]; uint2 u; };
__device__ __forceinline__ void split4(float4 a, uint2& hi, uint2& lo) {
    float v[4] = {a.x, a.y, a.z, a.w};
    Pack4 ph, pl;
#pragma unroll
    for (int i = 0; i < 4; i++) {
        __nv_bfloat16 h = __float2bfloat16(v[i]);
        ph.b[i] = h;
        pl.b[i] = __float2bfloat16(v[i] - __bfloat162float(h));
    }
    hi = ph.u; lo = pl.u;
}
__device__ __forceinline__ uint32_t split2(float x, float y, uint32_t& lo) {
    __nv_bfloat16 hx = __float2bfloat16(x), hy = __float2bfloat16(y);
    __nv_bfloat16 lx = __float2bfloat16(x - __bfloat162float(hx));
    __nv_bfloat16 ly = __float2bfloat16(y - __bfloat162float(hy));
    uint16_t uhx = *(uint16_t*)&hx, uhy = *(uint16_t*)&hy;
    uint16_t ulx = *(uint16_t*)&lx, uly = *(uint16_t*)&ly;
    lo = (uint32_t)ulx | ((uint32_t)uly << 16);
    return (uint32_t)uhx | ((uint32_t)uhy << 16);
}

// smem: 1KB mbar header + 3 stages x 64KB
#define T_A_HI 0
#define T_A_LO 16384
#define T_B_HI 32768
#define T_B_LO 49152
#define STAGE_SZ 65536
#define SMEMSZ (1024 + 1024 + 3 * STAGE_SZ)

// ---------------- prep: weights (+ fp32 W2 master) + h0 split ----------------
__global__ void prep_kernel(const float* __restrict__ W_msg,
                            const float* __restrict__ W_ih,
                            const float* __restrict__ W_hh,
                            const float* __restrict__ b_ih,
                            const float* __restrict__ b_hh) {
    int t = blockIdx.x * blockDim.x + threadIdx.x;
    int stride = gridDim.x * blockDim.x;
    for (int i = t; i < 128 * 256; i += stride) {      // W1[n][k] = W_msg[n][k]
        int n = i >> 8, k = i & 255;
        float w = W_msg[i];
        __nv_bfloat16 h = __float2bfloat16(w);
        size_t off = tsw(k >> 6, n, (k & 63) * 2);
        *(__nv_bfloat16*)((char*)g_W1h + off) = h;
        *(__nv_bfloat16*)((char*)g_W1l + off) = __float2bfloat16(w - __bfloat162float(h));
    }
    for (int i = t; i < 512 * 256; i += stride) {      // W2 permuted rows n=4j+g
        int n = i >> 8, k = i & 255;
        int j = n >> 2, g = n & 3;
        int wrow = g * HID + j;
        float w = (k < HID) ? W_ih[wrow * HID + k] : W_hh[wrow * HID + (k - HID)];
        g_W2f[n * 256 + k] = w;
        if (k >= HID) {                                // h-half split is step-invariant
            __nv_bfloat16 h = __float2bfloat16(w);
            size_t off = tsw((n >> 7) * 4 + (k >> 6), n & 127, (k & 63) * 2);
            *(__nv_bfloat16*)((char*)g_W2h + off) = h;
            *(__nv_bfloat16*)((char*)g_W2l + off) = __float2bfloat16(w - __bfloat162float(h));
        }
    }
    for (int i = t; i < 4 * HID; i += stride) g_bias[i] = b_ih[i] + b_hh[i];
    // h0 split -> XH[0]
    for (int i = t; i < NP * 16; i += stride) {
        int grow = i >> 4, q = i & 15;
        const float* src = &g_hA[(size_t)grow * HID + q * 8];
        float4 v0 = *(const float4*)src, v1 = *(const float4*)(src + 4);
        uint4 hi, lo; split8(v0, v1, hi, lo);
        int blk = grow >> 7, row = grow & 127;
        size_t off = tsw(blk * 2 + (q >> 3), row, (q & 7) * 16);
        *(uint4*)((char*)g_XHh[0] + off) = hi;
        *(uint4*)((char*)g_XHl[0] + off) = lo;
    }
}

// ---------------- CSR build ----------------
__global__ void degcnt_kernel(const int* __restrict__ ei) {
    int i = blockIdx.x * blockDim.x + threadIdx.x;
    if (i < 2 * N_EDGES) atomicAdd(&g_degi[ei[i]], 1);
}

__global__ void scan_kernel() {       // single block, 1024 threads
    __shared__ int part[1024];
    int t = threadIdx.x;
    const int CH = (N_VARS + 1023) / 1024;
    int base = t * CH;
    int s = 0;
    for (int i = 0; i < CH; i++) {
        int idx = base + i;
        if (idx < N_VARS) s += g_degi[idx];
    }
    part[t] = s;
    __syncthreads();
    int val = s;
#pragma unroll
    for (int d = 1; d < 1024; d <<= 1) {
        int v = (t >= d) ? part[t - d] : 0;
        __syncthreads();
        part[t] += v;
        __syncthreads();
    }
    int excl = part[t] - val;
    int run = excl;
    for (int i = 0; i < CH; i++) {
        int idx = base + i;
        if (idx < N_VARS) {
            g_off[idx] = run;
            int d = g_degi[idx];
            g_degf[idx] = (float)d;
            run += d;
        }
    }
    if (t == 1023) g_off[N_VARS] = run;
}

__global__ void fill_kernel(const int* __restrict__ ei) {
    int i = blockIdx.x * blockDim.x + threadIdx.x;
    if (i >= 2 * N_EDGES) return;
    int s, d;
    if (i < N_EDGES) { s = ei[i]; d = ei[N_EDGES + i]; }
    else             { s = ei[i]; d = ei[i - N_EDGES]; }
    int pos = atomicAdd(&g_cur[d], 1);
    g_adj[g_off[d] + pos] = s;
}

// ---------------- CSR gather -> X1 = split([agg | deg*h]) tiled-swizzled ----------------
__global__ void gather_kernel(const float* __restrict__ hin) {
    int w = (blockIdx.x * blockDim.x + threadIdx.x) >> 5;
    int lane = threadIdx.x & 31;
    if (w >= N_VARS) return;
    int e = g_off[w], end = g_off[w + 1];
    int c4 = lane * 4;
    float4 s0 = make_float4(0, 0, 0, 0), s1 = make_float4(0, 0, 0, 0);
    float4 s2 = make_float4(0, 0, 0, 0), s3 = make_float4(0, 0, 0, 0);
    for (; e + 4 <= end; e += 4) {
        int u0 = g_adj[e], u1 = g_adj[e + 1], u2 = g_adj[e + 2], u3 = g_adj[e + 3];
        float4 a = *(const float4*)&hin[(size_t)u0 * HID + c4];
        float4 b = *(const float4*)&hin[(size_t)u1 * HID + c4];
        float4 c = *(const float4*)&hin[(size_t)u2 * HID + c4];
        float4 d = *(const float4*)&hin[(size_t)u3 * HID + c4];
        s0.x += a.x; s0.y += a.y; s0.z += a.z; s0.w += a.w;
        s1.x += b.x; s1.y += b.y; s1.z += b.z; s1.w += b.w;
        s2.x += c.x; s2.y += c.y; s2.z += c.z; s2.w += c.w;
        s3.x += d.x; s3.y += d.y; s3.z += d.z; s3.w += d.w;
    }
    for (; e < end; e++) {
        int u = g_adj[e];
        float4 a = *(const float4*)&hin[(size_t)u * HID + c4];
        s0.x += a.x; s0.y += a.y; s0.z += a.z; s0.w += a.w;
    }
    s0.x += s1.x + s2.x + s3.x; s0.y += s1.y + s2.y + s3.y;
    s0.z += s1.z + s2.z + s3.z; s0.w += s1.w + s2.w + s3.w;
    int blk = w >> 7, row = w & 127;
    int kb = (c4 & 63) * 2;
    uint2 hi, lo;
    split4(s0, hi, lo);
    size_t off = tsw(blk * 4 + (c4 >> 6), row, kb);
    *(uint2*)((char*)g_X1h + off) = hi;
    *(uint2*)((char*)g_X1l + off) = lo;
    float d = g_degf[w];
    float4 hv = *(const float4*)&hin[(size_t)w * HID + c4];
    hv.x *= d; hv.y *= d; hv.z *= d; hv.w *= d;
    split4(hv, hi, lo);
    off = tsw(blk * 4 + 2 + (c4 >> 6), row, kb);
    *(uint2*)((char*)g_X1h + off) = hi;
    *(uint2*)((char*)g_X1l + off) = lo;
}

// ---------------- bulk-copy stage issue (thread 0) — dual A base ----------------
__device__ __forceinline__ void issue_stage(uint32_t st,
        const __nv_bfloat16* A0h, const __nv_bfloat16* A0l, int a0tb,
        const __nv_bfloat16* A1h, const __nv_bfloat16* A1l, int a1tb,
        const __nv_bfloat16* Bh, const __nv_bfloat16* Bl, int btb,
        int c, uint32_t mbar) {
    MBAR_EXPECT(mbar, 4 * 16384);
    const __nv_bfloat16 *ah, *al;
    int tb;
    if (c < 2) { ah = A0h; al = A0l; tb = a0tb + c; }
    else       { ah = A1h; al = A1l; tb = a1tb + c - 2; }
    bulk_cp(st + T_A_HI, ah + (size_t)tb * 8192, 16384, mbar);
    bulk_cp(st + T_A_LO, al + (size_t)tb * 8192, 16384, mbar);
    bulk_cp(st + T_B_HI, Bh + (size_t)(btb + c) * 8192, 16384, mbar);
    bulk_cp(st + T_B_LO, Bl + (size_t)(btb + c) * 8192, 16384, mbar);
}

// ---------------- warp-tile compute core (one K-chunk of 64), 32x32 warp tile ----------------
__device__ __forceinline__ void chunk_compute(uint32_t sb, int warpRow, int warpCol,
                                              int lane, float acc[2][4][4]) {
#pragma unroll
    for (int ks = 0; ks < 4; ks++) {
        uint32_t aH[2][4], aL[2][4];
#pragma unroll
        for (int mt = 0; mt < 2; mt++) {
            uint32_t off = (uint32_t)((warpRow + mt * 16 + (lane & 15)) * 128
                                      + ks * 32 + ((lane >> 4) & 1) * 16);
            uint32_t sw = SWZ(off);
            LDSM4(aH[mt], sb + T_A_HI + sw);
            LDSM4(aL[mt], sb + T_A_LO + sw);
        }
#pragma unroll
        for (int np = 0; np < 2; np++) {
            uint32_t bH[4], bL[4];
            uint32_t off = (uint32_t)((warpCol + np * 16 + ((lane >> 4) & 1) * 8 + (lane & 7)) * 128
                                      + ks * 32 + ((lane >> 3) & 1) * 16);
            uint32_t sw = SWZ(off);
            LDSM4(bH, sb + T_B_HI + sw);
            LDSM4(bL, sb + T_B_LO + sw);
#pragma unroll
            for (int mt = 0; mt < 2; mt++) {
#pragma unroll
                for (int nt = 0; nt < 2; nt++) {
                    float* c = acc[mt][np * 2 + nt];
                    MMA(c, aH[mt], bH[nt * 2], bH[nt * 2 + 1]);
                    MMA(c, aH[mt], bL[nt * 2], bL[nt * 2 + 1]);
                    MMA(c, aL[mt], bH[nt * 2], bH[nt * 2 + 1]);
                }
            }
        }
    }
}

// ---------------- shared GEMM pipeline: bulk copies, 3 stages, 4 chunks ----------------
#define GEMM_PIPELINE(A0h, A0l, A0TB, A1h, A1l, A1TB, Bh, Bl, BTB)                     \
    {                                                                                  \
        uint32_t mb0 = sb, mb1 = sb + 8, mb2 = sb + 16;                                \
        uint32_t st0 = sb + 1024, st1 = st0 + STAGE_SZ, st2 = st0 + 2 * STAGE_SZ;      \
        if (tid == 0) {                                                                \
            MBAR_INIT(mb0, 1); MBAR_INIT(mb1, 1); MBAR_INIT(mb2, 1);                   \
            issue_stage(st0, A0h, A0l, A0TB, A1h, A1l, A1TB, Bh, Bl, BTB, 0, mb0);     \
            issue_stage(st1, A0h, A0l, A0TB, A1h, A1l, A1TB, Bh, Bl, BTB, 1, mb1);     \
            issue_stage(st2, A0h, A0l, A0TB, A1h, A1l, A1TB, Bh, Bl, BTB, 2, mb2);     \
        }                                                                              \
        __syncthreads();                                                               \
        mbar_wait(mb0, 0);                                                             \
        chunk_compute(st0, warpRow, warpCol, lane, acc);                               \
        __syncthreads();                                                               \
        if (tid == 0)                                                                  \
            issue_stage(st0, A0h, A0l, A0TB, A1h, A1l, A1TB, Bh, Bl, BTB, 3, mb0);     \
        mbar_wait(mb1, 0);                                                             \
        chunk_compute(st1, warpRow, warpCol, lane, acc);                               \
        mbar_wait(mb2, 0);                                                             \
        chunk_compute(st2, warpRow, warpCol, lane, acc);                               \
        mbar_wait(mb0, 1);                                                             \
        chunk_compute(st0, warpRow, warpCol, lane, acc);                               \
        __syncthreads();                                                               \
    }

// ---------------- rec = (X1 @ W1^T) * var_reg -> split into XR; fused BN stats ----------------
__global__ void __launch_bounds__(512, 1)
rec_mma(const float* __restrict__ var_reg) {
    extern __shared__ char smraw[];
    uint32_t sb0 = smem_u32(smraw);
    uint32_t sb = (sb0 + 1023) & ~1023u;
    const int tid = threadIdx.x;
    const int wid = tid >> 5, lane = tid & 31;
    const int rowBase = blockIdx.x * 128;
    const int warpRow = (wid >> 2) * 32, warpCol = (wid & 3) * 32;

    float acc[2][4][4];
#pragma unroll
    for (int m = 0; m < 2; m++)
#pragma unroll
        for (int n = 0; n < 4; n++)
#pragma unroll
            for (int c = 0; c < 4; c++) acc[m][n][c] = 0.f;

    GEMM_PIPELINE(g_X1h, g_X1l, blockIdx.x * 4,
                  g_X1h, g_X1l, blockIdx.x * 4 + 2,
                  g_W1h, g_W1l, 0)

    // epilogue: scale by var_reg, split-store into XR tiles, fused column stats
    float s[4][2] = {}, q[4][2] = {};
    const int blk = blockIdx.x;
#pragma unroll
    for (int mt = 0; mt < 2; mt++) {
        int r0 = rowBase + warpRow + mt * 16 + (lane >> 2);
        int r1 = r0 + 8;
        float vr0 = (r0 < N_VARS) ? var_reg[r0] : 0.f;
        float vr1 = (r1 < N_VARS) ? var_reg[r1] : 0.f;
#pragma unroll
        for (int n8 = 0; n8 < 4; n8++) {
            int col = warpCol + n8 * 8 + 2 * (lane & 3);
            float* c = acc[mt][n8];
            float v00 = c[0] * vr0, v01 = c[1] * vr0;
            float v10 = c[2] * vr1, v11 = c[3] * vr1;
            uint32_t lo0, lo1;
            uint32_t hi0 = split2(v00, v01, lo0);
            uint32_t hi1 = split2(v10, v11, lo1);
            int tile = blk * 2 + (col >> 6);
            int kb = (col & 63) * 2;
            size_t off0 = tsw(tile, r0 & 127, kb);
            size_t off1 = tsw(tile, r1 & 127, kb);
            *(uint32_t*)((char*)g_XRh + off0) = hi0;
            *(uint32_t*)((char*)g_XRl + off0) = lo0;
            *(uint32_t*)((char*)g_XRh + off1) = hi1;
            *(uint32_t*)((char*)g_XRl + off1) = lo1;
            s[n8][0] += v00 + v10;  q[n8][0] += v00 * v00 + v10 * v10;
            s[n8][1] += v01 + v11;  q[n8][1] += v01 * v01 + v11 * v11;
        }
    }
#pragma unroll
    for (int o = 4; o <= 16; o <<= 1) {
#pragma unroll
        for (int n8 = 0; n8 < 4; n8++) {
#pragma unroll
            for (int p = 0; p < 2; p++) {
                s[n8][p] += __shfl_xor_sync(0xffffffffu, s[n8][p], o);
                q[n8][p] += __shfl_xor_sync(0xffffffffu, q[n8][p], o);
            }
        }
    }
    if (lane < 4) {
#pragma unroll
        for (int n8 = 0; n8 < 4; n8++) {
#pragma unroll
            for (int p = 0; p < 2; p++) {
                int col = warpCol + n8 * 8 + 2 * lane + p;
                atomicAdd(&g_stats[col], s[n8][p]);
                atomicAdd(&g_stats[HID + col], q[n8][p]);
            }
        }
    }
}

// ---------------- w2scale: fold BN affine into W2 rec-half + bias2 ----------------
__global__ void w2scale(const float* __restrict__ gamma, const float* __restrict__ beta) {
    __shared__ float sA[HID], sB[HID];
    int t = threadIdx.x;                  // 256 threads
    if (t < HID) {
        float mean = g_stats[t] * (1.0f / N_VARS);
        float var = g_stats[HID + t] * (1.0f / N_VARS) - mean * mean;
        float a = gamma[t] * rsqrtf(var + BN_EPS);
        sA[t] = a;
        sB[t] = beta[t] - mean * a;
    }
    __syncthreads();
    int b = blockIdx.x;
    if (b < 16) {
        // rescale rec-half of W2 (512 n x 128 k): 4096 elements per block
#pragma unroll
        for (int r = 0; r < 16; r++) {
            int e = b * 4096 + t + r * 256;
            int n = e >> 7, k = e & 127;
            float w = g_W2f[n * 256 + k] * sA[k];
            __nv_bfloat16 h = __float2bfloat16(w);
            size_t off = tsw((n >> 7) * 4 + (k >> 6), n & 127, (k & 63) * 2);
            *(__nv_bfloat16*)((char*)g_W2h + off) = h;
            *(__nv_bfloat16*)((char*)g_W2l + off) = __float2bfloat16(w - __bfloat162float(h));
        }
    } else {
        // bias2[n] = bias[n] + sum_{k<128} sB[k]*W2f[n,k]
        for (int n = t; n < 512; n += 256) {
            float acc = g_bias[n];
            const float* wrow = &g_W2f[n * 256];
#pragma unroll 8
            for (int k = 0; k < HID; k++) acc = fmaf(sB[k], wrow[k], acc);
            g_bias2[n] = acc;
        }
    }
}

// ---------------- gates = [split(rec)|split(h)] @ W2'^T + LSTM; split(h') -> XH[par^1] ----------------
__global__ void __launch_bounds__(512, 1)
gates_mma(float* __restrict__ hout, int par) {
    extern __shared__ char smraw[];
    uint32_t sb0 = smem_u32(smraw);
    uint32_t sb = (sb0 + 1023) & ~1023u;
    char* smp = smraw + (sb - sb0);
    const int tid = threadIdx.x;
    const int wid = tid >> 5, lane = tid & 31;
    const int rowBase = blockIdx.x * 128;
    const int by = blockIdx.y;
    const int warpRow = (wid >> 2) * 32, warpCol = (wid & 3) * 32;

    // reset BN stats for the next step (after w2scale consumed them)
    if (blockIdx.x == 0 && by == 0 && tid < 2 * HID) g_stats[tid] = 0.f;

    float acc[2][4][4];
#pragma unroll
    for (int m = 0; m < 2; m++)
#pragma unroll
        for (int n = 0; n < 4; n++)
#pragma unroll
            for (int c = 0; c < 4; c++) acc[m][n][c] = 0.f;

    GEMM_PIPELINE(g_XRh, g_XRl, blockIdx.x * 2,
                  g_XHh[par], g_XHl[par], blockIdx.x * 2,
                  g_W2h, g_W2l, by * 4)

    // stage gate tile to smem overlay, then fused LSTM pointwise
    float* Cs = (float*)(smp + 1024);          // 128 x 128 fp32 = 64KB
#pragma unroll
    for (int mt = 0; mt < 2; mt++) {
        int r0 = warpRow + mt * 16 + (lane >> 2);
#pragma unroll
        for (int n8 = 0; n8 < 4; n8++) {
            int col = warpCol + n8 * 8 + 2 * (lane & 3);
            float* c = acc[mt][n8];
            *(float2*)&Cs[r0 * 128 + col]       = make_float2(c[0], c[1]);
            *(float2*)&Cs[(r0 + 8) * 128 + col] = make_float2(c[2], c[3]);
        }
    }
    __syncthreads();
    __nv_bfloat16* XHh_w = g_XHh[par ^ 1];
    __nv_bfloat16* XHl_w = g_XHl[par ^ 1];
#pragma unroll
    for (int it = 0; it < 8; it++) {
        int cell = tid + 512 * it;
        int row = cell >> 5, jq = cell & 31;
        int grow = rowBase + row;
        int j = by * 32 + jq;
        float4 gt = *(const float4*)&Cs[row * 128 + jq * 4];   // i,f,g,o
        float4 b4 = *(const float4*)&g_bias2[4 * j];
        size_t idx = (size_t)grow * HID + j;
        float ig = gt.x + b4.x;
        float fg = gt.y + b4.y;
        float gg = gt.z + b4.z;
        float og = gt.w + b4.w;
        float cn = sigf(fg) * g_c[idx] + sigf(ig) * tanhf(gg);
        g_c[idx] = cn;
        float hv = sigf(og) * tanhf(cn);
        hout[idx] = hv;
        __nv_bfloat16 hb = __float2bfloat16(hv);
        __nv_bfloat16 lb = __float2bfloat16(hv - __bfloat162float(hb));
        int blk = grow >> 7, trow = grow & 127;
        size_t off = tsw(blk * 2 + (j >> 6), trow, (j & 63) * 2);
        *(__nv_bfloat16*)((char*)XHh_w + off) = hb;
        *(__nv_bfloat16*)((char*)XHl_w + off) = lb;
    }
}

// ---------------- output: softmax(h @ W_out^T) ----------------
__global__ void out_kernel(const float* __restrict__ hin,
                           const float* __restrict__ W_out,
                           float* __restrict__ out) {
    int v = (blockIdx.x * blockDim.x + threadIdx.x) >> 5;
    int lane = threadIdx.x & 31;
    if (v >= N_VARS) return;
    float p0 = 0.f, p1 = 0.f, p2 = 0.f;
#pragma unroll
    for (int q = 0; q < 4; q++) {
        int col = lane + q * 32;
        float hv = hin[(size_t)v * HID + col];
        p0 = fmaf(hv, __ldg(&W_out[col]), p0);
        p1 = fmaf(hv, __ldg(&W_out[HID + col]), p1);
        p2 = fmaf(hv, __ldg(&W_out[2 * HID + col]), p2);
    }
#pragma unroll
    for (int o = 16; o > 0; o >>= 1) {
        p0 += __shfl_xor_sync(0xffffffffu, p0, o);
        p1 += __shfl_xor_sync(0xffffffffu, p1, o);
        p2 += __shfl_xor_sync(0xffffffffu, p2, o);
    }
    if (lane == 0) {
        float m = fmaxf(p0, fmaxf(p1, p2));
        float e0 = expf(p0 - m), e1 = expf(p1 - m), e2 = expf(p2 - m);
        float inv = 1.f / (e0 + e1 + e2);
        out[v * 3 + 0] = e0 * inv;
        out[v * 3 + 1] = e1 * inv;
        out[v * 3 + 2] = e2 * inv;
    }
}

// ---------------- launch ----------------
extern "C" void kernel_launch(void* const* d_in, const int* in_sizes, int n_in,
                              void* d_out, int out_size) {
    const float* h0      = (const float*)d_in[0];
    const float* var_reg = (const float*)d_in[1];
    const float* W_msg   = (const float*)d_in[2];
    const float* gamma   = (const float*)d_in[3];
    const float* beta    = (const float*)d_in[4];
    const float* W_ih    = (const float*)d_in[5];
    const float* W_hh    = (const float*)d_in[6];
    const float* b_ih    = (const float*)d_in[7];
    const float* b_hh    = (const float*)d_in[8];
    const float* W_out   = (const float*)d_in[9];
    const int*   ei      = (const int*)d_in[10];
    (void)in_sizes; (void)n_in;

    cudaFuncSetAttribute(rec_mma,   cudaFuncAttributeMaxDynamicSharedMemorySize, SMEMSZ);
    cudaFuncSetAttribute(gates_mma, cudaFuncAttributeMaxDynamicSharedMemorySize, SMEMSZ);

    float *hA, *hB, *cbuf, *stats;
    int *degi, *cur;
    cudaGetSymbolAddress((void**)&hA, g_hA);
    cudaGetSymbolAddress((void**)&hB, g_hB);
    cudaGetSymbolAddress((void**)&cbuf, g_c);
    cudaGetSymbolAddress((void**)&degi, g_degi);
    cudaGetSymbolAddress((void**)&cur, g_cur);
    cudaGetSymbolAddress((void**)&stats, g_stats);

    cudaStream_t s = 0;
    cudaMemcpyAsync(hA, h0, (size_t)N_VARS * HID * sizeof(float),
                    cudaMemcpyDeviceToDevice, s);
    cudaMemsetAsync(hA + (size_t)N_VARS * HID, 0,
                    (size_t)(NP - N_VARS) * HID * sizeof(float), s);
    cudaMemsetAsync(cbuf, 0, (size_t)NP * HID * sizeof(float), s);
    cudaMemsetAsync(degi, 0, (size_t)NP * sizeof(int), s);
    cudaMemsetAsync(cur, 0, (size_t)NP * sizeof(int), s);
    cudaMemsetAsync(stats, 0, 2 * HID * sizeof(float), s);

    prep_kernel<<<512, 256, 0, s>>>(W_msg, W_ih, W_hh, b_ih, b_hh);
    degcnt_kernel<<<(2 * N_EDGES + 255) / 256, 256, 0, s>>>(ei);
    scan_kernel<<<1, 1024, 0, s>>>();
    fill_kernel<<<(2 * N_EDGES + 255) / 256, 256, 0, s>>>(ei);

    const float* hin = hA;
    float* hout = hB;
    for (int st = 0; st < STEPS; ++st) {
        int par = st & 1;
        gather_kernel<<<(N_VARS * 32 + 255) / 256, 256, 0, s>>>(hin);
        rec_mma<<<NBLK, 512, SMEMSZ, s>>>(var_reg);
        w2scale<<<17, 256, 0, s>>>(gamma, beta);
        gates_mma<<<dim3(NBLK, 4), 512, SMEMSZ, s>>>(hout, par);
        const float* tmp = hout;
        hout = (float*)hin;
        hin = tmp;
    }
    out_kernel<<<(N_VARS * 32 + 255) / 256, 256, 0, s>>>(hin, W_out, (float*)d_out);
}

// round 11
// speedup vs baseline: 1.0352x; 1.0352x over previous
#include <cuda_runtime.h>
#include <cuda_bf16.h>
#include <math.h>
#include <stdint.h>

#define N_VARS 50000
#define HID 128
#define N_EDGES 400000
#define NP 50048            // 391 * 128
#define NBLK (NP / 128)     // 391
#define STEPS 4
#define BN_EPS 1e-5f

// ---------------- static device scratch ----------------
__device__ float g_hA[NP * HID];
__device__ float g_hB[NP * HID];
__device__ float g_c[NP * HID];
__device__ float g_rec[NP * HID];
__device__ float g_degf[NP];
__device__ int   g_degi[NP];
__device__ int   g_off[NP + 1];
__device__ int   g_cur[NP];
__device__ int   g_adj[2 * N_EDGES];
__device__ __align__(16) __nv_bfloat16 g_W1h[128 * 256];   // rec weights  [n][k] linear
__device__ __align__(16) __nv_bfloat16 g_W1l[128 * 256];
__device__ __align__(16) __nv_bfloat16 g_W2h[512 * 256];   // gate weights [n=4j+g][k] linear
__device__ __align__(16) __nv_bfloat16 g_W2l[512 * 256];
// ping-pong buffers: [BN(rec) | h] — gates reads par, writes h-half of par^1
__device__ __align__(16) __nv_bfloat16 g_X2h[2][NP * 256];
__device__ __align__(16) __nv_bfloat16 g_X2l[2][NP * 256];
__device__ float g_bias[4 * HID];
__device__ float g_stats[2 * HID];

__device__ __forceinline__ float sigf(float x) { return 1.0f / (1.0f + expf(-x)); }

__device__ __forceinline__ uint32_t smem_u32(const void* p) {
    uint32_t a;
    asm("{ .reg .u64 t; cvta.to.shared.u64 t, %1; cvt.u32.u64 %0, t; }" : "=r"(a) : "l"(p));
    return a;
}
#define SWZ(o) ((o) ^ (((o) >> 3) & 0x70))

#define LDSM4(R, A) \
    asm volatile("ldmatrix.sync.aligned.m8n8.x4.shared.b16 {%0,%1,%2,%3}, [%4];" \
                 : "=r"((R)[0]), "=r"((R)[1]), "=r"((R)[2]), "=r"((R)[3]) : "r"(A))

#define MMA(C, A, B0, B1) \
    asm volatile("mma.sync.aligned.m16n8k16.row.col.f32.bf16.bf16.f32 " \
                 "{%0,%1,%2,%3},{%4,%5,%6,%7},{%8,%9},{%0,%1,%2,%3};" \
                 : "+f"((C)[0]), "+f"((C)[1]), "+f"((C)[2]), "+f"((C)[3]) \
                 : "r"((A)[0]), "r"((A)[1]), "r"((A)[2]), "r"((A)[3]), "r"(B0), "r"(B1))

#define CP16(dst_u32, src_ptr) \
    asm volatile("cp.async.cg.shared.global [%0], [%1], 16;" \
                 :: "r"(dst_u32), "l"(src_ptr))
#define CP_COMMIT() asm volatile("cp.async.commit_group;")
#define CP_WAIT(n)  asm volatile("cp.async.wait_group %0;" :: "n"(n))

union Pack8 { __nv_bfloat16 b[8]; uint4 u; };
__device__ __forceinline__ void split8(float4 a, float4 b, uint4& hi, uint4& lo) {
    float v[8] = {a.x, a.y, a.z, a.w, b.x, b.y, b.z, b.w};
    Pack8 ph, pl;
#pragma unroll
    for (int i = 0; i < 8; i++) {
        __nv_bfloat16 h = __float2bfloat16(v[i]);
        ph.b[i] = h;
        pl.b[i] = __float2bfloat16(v[i] - __bfloat162float(h));
    }
    hi = ph.u; lo = pl.u;
}
union Pack4 { __nv_bfloat16 b[4]; uint2 u; };
__device__ __forceinline__ void split4(float4 a, uint2& hi, uint2& lo) {
    float v[4] = {a.x, a.y, a.z, a.w};
    Pack4 ph, pl;
#pragma unroll
    for (int i = 0; i < 4; i++) {
        __nv_bfloat16 h = __float2bfloat16(v[i]);
        ph.b[i] = h;
        pl.b[i] = __float2bfloat16(v[i] - __bfloat162float(h));
    }
    hi = ph.u; lo = pl.u;
}

// ---- gates smem: 3 stages x (A_hi, A_lo, B_hi, B_lo) 16KB each ----
#define T_A_HI 0
#define T_A_LO 16384
#define T_B_HI 32768
#define T_B_LO 49152
#define STAGE_SZ 65536
#define SMEMSZ_G (1024 + 3 * STAGE_SZ)

// ---- gather_rec smem: A-resident (4 chunks) + 2 B stages ----
#define R_AH 0
#define R_AL 65536
#define R_B0 131072
#define R_B1 163840
#define SMEMSZ_R (1024 + 196608)

// ---------------- prep: bf16-split weights, fused bias ----------------
__global__ void prep_kernel(const float* __restrict__ W_msg,
                            const float* __restrict__ W_ih,
                            const float* __restrict__ W_hh,
                            const float* __restrict__ b_ih,
                            const float* __restrict__ b_hh) {
    int t = blockIdx.x * blockDim.x + threadIdx.x;
    int stride = gridDim.x * blockDim.x;
    for (int i = t; i < 128 * 256; i += stride) {
        float w = W_msg[i];
        __nv_bfloat16 h = __float2bfloat16(w);
        g_W1h[i] = h;
        g_W1l[i] = __float2bfloat16(w - __bfloat162float(h));
    }
    for (int i = t; i < 512 * 256; i += stride) {
        int n = i >> 8, k = i & 255;
        int j = n >> 2, g = n & 3;
        int wrow = g * HID + j;
        float w = (k < HID) ? W_ih[wrow * HID + k] : W_hh[wrow * HID + (k - HID)];
        __nv_bfloat16 h = __float2bfloat16(w);
        g_W2h[i] = h;
        g_W2l[i] = __float2bfloat16(w - __bfloat162float(h));
    }
    for (int i = t; i < 4 * HID; i += stride) g_bias[i] = b_ih[i] + b_hh[i];
}

// ---------------- CSR build ----------------
__global__ void degcnt_kernel(const int* __restrict__ ei) {
    int i = blockIdx.x * blockDim.x + threadIdx.x;
    if (i < 2 * N_EDGES) atomicAdd(&g_degi[ei[i]], 1);
}

__global__ void scan_kernel() {       // single block, 1024 threads
    __shared__ int part[1024];
    int t = threadIdx.x;
    const int CH = (N_VARS + 1023) / 1024;
    int base = t * CH;
    int s = 0;
    for (int i = 0; i < CH; i++) {
        int idx = base + i;
        if (idx < N_VARS) s += g_degi[idx];
    }
    part[t] = s;
    __syncthreads();
    int val = s;
#pragma unroll
    for (int d = 1; d < 1024; d <<= 1) {
        int v = (t >= d) ? part[t - d] : 0;
        __syncthreads();
        part[t] += v;
        __syncthreads();
    }
    int excl = part[t] - val;
    int run = excl;
    for (int i = 0; i < CH; i++) {
        int idx = base + i;
        if (idx < N_VARS) {
            g_off[idx] = run;
            int d = g_degi[idx];
            g_degf[idx] = (float)d;
            run += d;
        }
    }
    if (t == 1023) g_off[N_VARS] = run;
}

__global__ void fill_kernel(const int* __restrict__ ei) {
    int i = blockIdx.x * blockDim.x + threadIdx.x;
    if (i >= 2 * N_EDGES) return;
    int s, d;
    if (i < N_EDGES) { s = ei[i]; d = ei[N_EDGES + i]; }
    else             { s = ei[i]; d = ei[i - N_EDGES]; }
    int pos = atomicAdd(&g_cur[d], 1);
    g_adj[g_off[d] + pos] = s;
}

// ---------------- h0 split -> X2[0] h-part (once) ----------------
__global__ void h0split(const float* __restrict__ hin) {
    int idx = blockIdx.x * blockDim.x + threadIdx.x;
    if (idx >= NP * 16) return;
    int row = idx >> 4, i = idx & 15;
    const float* src = &hin[(size_t)row * HID + i * 8];
    float4 v0 = *(const float4*)src, v1 = *(const float4*)(src + 4);
    uint4 hi, lo; split8(v0, v1, hi, lo);
    ((uint4*)g_X2h[0])[row * 32 + 16 + i] = hi;
    ((uint4*)g_X2l[0])[row * 32 + 16 + i] = lo;
}

// ---------------- warp-tile compute core, parameterized bases ----------------
__device__ __forceinline__ void chunk_compute2(uint32_t aHb, uint32_t aLb,
                                               uint32_t bHb, uint32_t bLb,
                                               int warpRow, int warpCol,
                                               int lane, float acc[2][4][4]) {
#pragma unroll
    for (int ks = 0; ks < 4; ks++) {
        uint32_t aH[2][4], aL[2][4];
#pragma unroll
        for (int mt = 0; mt < 2; mt++) {
            uint32_t off = (uint32_t)((warpRow + mt * 16 + (lane & 15)) * 128
                                      + ks * 32 + ((lane >> 4) & 1) * 16);
            uint32_t sw = SWZ(off);
            LDSM4(aH[mt], aHb + sw);
            LDSM4(aL[mt], aLb + sw);
        }
#pragma unroll
        for (int np = 0; np < 2; np++) {
            uint32_t bH[4], bL[4];
            uint32_t off = (uint32_t)((warpCol + np * 16 + ((lane >> 4) & 1) * 8 + (lane & 7)) * 128
                                      + ks * 32 + ((lane >> 3) & 1) * 16);
            uint32_t sw = SWZ(off);
            LDSM4(bH, bHb + sw);
            LDSM4(bL, bLb + sw);
#pragma unroll
            for (int mt = 0; mt < 2; mt++) {
#pragma unroll
                for (int nt = 0; nt < 2; nt++) {
                    float* c = acc[mt][np * 2 + nt];
                    MMA(c, aH[mt], bH[nt * 2], bH[nt * 2 + 1]);
                    MMA(c, aH[mt], bL[nt * 2], bL[nt * 2 + 1]);
                    MMA(c, aL[mt], bH[nt * 2], bH[nt * 2 + 1]);
                }
            }
        }
    }
}

// ---------------- cp.async staging for gates (A+B per chunk) ----------------
__device__ __forceinline__ void stage_tiles(uint32_t sbase,
                                            const uint4* __restrict__ Ah,
                                            const uint4* __restrict__ Al,
                                            const uint4* __restrict__ Bh,
                                            const uint4* __restrict__ Bl,
                                            int aBase32, int bBase32, int k8, int tid) {
#pragma unroll
    for (int idx = tid; idx < 1024; idx += 512) {
        int row = idx >> 3, i = idx & 7;
        uint32_t sw = SWZ((uint32_t)(row * 128 + i * 16));
        int ga = aBase32 + row * 32 + k8 + i;
        int gb = bBase32 + row * 32 + k8 + i;
        CP16(sbase + T_A_HI + sw, Ah + ga);
        CP16(sbase + T_A_LO + sw, Al + ga);
        CP16(sbase + T_B_HI + sw, Bh + gb);
        CP16(sbase + T_B_LO + sw, Bl + gb);
    }
}

// ---------------- cp.async staging of a W1 B-tile (rec) ----------------
__device__ __forceinline__ void stage_B1(uint32_t bbase, int c, int tid) {
    const uint4* Wh = (const uint4*)g_W1h;
    const uint4* Wl = (const uint4*)g_W1l;
#pragma unroll
    for (int idx = tid; idx < 1024; idx += 512) {
        int row = idx >> 3, i = idx & 7;
        uint32_t sw = SWZ((uint32_t)(row * 128 + i * 16));
        int gi = row * 32 + c * 8 + i;
        CP16(bbase + sw, Wh + gi);
        CP16(bbase + 16384 + sw, Wl + gi);
    }
}

// ---------------- FUSED gather + rec GEMM ----------------
// Per CTA (128 rows): gather neighbor sums into swizzled smem A (bf16 hi/lo),
// prefetch W1 B-tiles meanwhile, then MMA. Epilogue: rec store + BN stats.
__global__ void __launch_bounds__(512, 1)
gather_rec(const float* __restrict__ hin, const float* __restrict__ var_reg) {
    extern __shared__ char smraw[];
    uint32_t sb0 = smem_u32(smraw);
    uint32_t sb = (sb0 + 1023) & ~1023u;
    char* smp = smraw + (sb - sb0);
    const int tid = threadIdx.x;
    const int wid = tid >> 5, lane = tid & 31;
    const int rowBase = blockIdx.x * 128;
    const int warpRow = (wid >> 2) * 32, warpCol = (wid & 3) * 32;

    // prefetch B chunks 0,1 while gathering
    stage_B1(sb + R_B0, 0, tid);  CP_COMMIT();
    stage_B1(sb + R_B1, 1, tid);  CP_COMMIT();

    // ---- gather phase: A = split([agg | deg*h]) into smem ----
    const int c4 = lane * 4;
    const int tile = c4 >> 6;
    const uint32_t kb = (uint32_t)((c4 & 63) * 2);
#pragma unroll 1
    for (int r = 0; r < 8; r++) {
        int lrow = wid * 8 + r;
        int grow = rowBase + lrow;
        float4 s0 = make_float4(0, 0, 0, 0), s1 = s0, s2 = s0, s3 = s0;
        float4 hv = make_float4(0, 0, 0, 0);
        if (grow < N_VARS) {
            int e = g_off[grow], end = g_off[grow + 1];
            for (; e + 4 <= end; e += 4) {
                int u0 = g_adj[e], u1 = g_adj[e + 1], u2 = g_adj[e + 2], u3 = g_adj[e + 3];
                float4 a = *(const float4*)&hin[(size_t)u0 * HID + c4];
                float4 b = *(const float4*)&hin[(size_t)u1 * HID + c4];
                float4 c = *(const float4*)&hin[(size_t)u2 * HID + c4];
                float4 d = *(const float4*)&hin[(size_t)u3 * HID + c4];
                s0.x += a.x; s0.y += a.y; s0.z += a.z; s0.w += a.w;
                s1.x += b.x; s1.y += b.y; s1.z += b.z; s1.w += b.w;
                s2.x += c.x; s2.y += c.y; s2.z += c.z; s2.w += c.w;
                s3.x += d.x; s3.y += d.y; s3.z += d.z; s3.w += d.w;
            }
            for (; e < end; e++) {
                int u = g_adj[e];
                float4 a = *(const float4*)&hin[(size_t)u * HID + c4];
                s0.x += a.x; s0.y += a.y; s0.z += a.z; s0.w += a.w;
            }
            float d = g_degf[grow];
            hv = *(const float4*)&hin[(size_t)grow * HID + c4];
            hv.x *= d; hv.y *= d; hv.z *= d; hv.w *= d;
        }
        s0.x += s1.x + s2.x + s3.x; s0.y += s1.y + s2.y + s3.y;
        s0.z += s1.z + s2.z + s3.z; s0.w += s1.w + s2.w + s3.w;
        uint32_t sw = SWZ((uint32_t)(lrow * 128) + kb);
        uint2 hi, lo;
        split4(s0, hi, lo);
        *(uint2*)(smp + R_AH + tile * 16384 + sw) = hi;
        *(uint2*)(smp + R_AL + tile * 16384 + sw) = lo;
        split4(hv, hi, lo);
        *(uint2*)(smp + R_AH + (2 + tile) * 16384 + sw) = hi;
        *(uint2*)(smp + R_AL + (2 + tile) * 16384 + sw) = lo;
    }

    float acc[2][4][4];
#pragma unroll
    for (int m = 0; m < 2; m++)
#pragma unroll
        for (int n = 0; n < 4; n++)
#pragma unroll
            for (int c = 0; c < 4; c++) acc[m][n][c] = 0.f;

    // ---- MMA phase: 4 chunks, B double-buffered ----
    CP_WAIT(1); __syncthreads();            // B0 ready + A visible
    chunk_compute2(sb + R_AH, sb + R_AL,
                   sb + R_B0, sb + R_B0 + 16384, warpRow, warpCol, lane, acc);
    __syncthreads();
    stage_B1(sb + R_B0, 2, tid); CP_COMMIT();
    CP_WAIT(1); __syncthreads();
    chunk_compute2(sb + R_AH + 16384, sb + R_AL + 16384,
                   sb + R_B1, sb + R_B1 + 16384, warpRow, warpCol, lane, acc);
    __syncthreads();
    stage_B1(sb + R_B1, 3, tid); CP_COMMIT();
    CP_WAIT(1); __syncthreads();
    chunk_compute2(sb + R_AH + 32768, sb + R_AL + 32768,
                   sb + R_B0, sb + R_B0 + 16384, warpRow, warpCol, lane, acc);
    CP_WAIT(0); __syncthreads();
    chunk_compute2(sb + R_AH + 49152, sb + R_AL + 49152,
                   sb + R_B1, sb + R_B1 + 16384, warpRow, warpCol, lane, acc);

    // ---- epilogue: scale by var_reg, store rec, fused column stats ----
    float s[4][2] = {}, q[4][2] = {};
#pragma unroll
    for (int mt = 0; mt < 2; mt++) {
        int r0 = rowBase + warpRow + mt * 16 + (lane >> 2);
        int r1 = r0 + 8;
        float vr0 = (r0 < N_VARS) ? var_reg[r0] : 0.f;
        float vr1 = (r1 < N_VARS) ? var_reg[r1] : 0.f;
#pragma unroll
        for (int n8 = 0; n8 < 4; n8++) {
            int col = warpCol + n8 * 8 + 2 * (lane & 3);
            float* c = acc[mt][n8];
            float v00 = c[0] * vr0, v01 = c[1] * vr0;
            float v10 = c[2] * vr1, v11 = c[3] * vr1;
            *(float2*)&g_rec[(size_t)r0 * HID + col] = make_float2(v00, v01);
            *(float2*)&g_rec[(size_t)r1 * HID + col] = make_float2(v10, v11);
            s[n8][0] += v00 + v10;  q[n8][0] += v00 * v00 + v10 * v10;
            s[n8][1] += v01 + v11;  q[n8][1] += v01 * v01 + v11 * v11;
        }
    }
#pragma unroll
    for (int o = 4; o <= 16; o <<= 1) {
#pragma unroll
        for (int n8 = 0; n8 < 4; n8++) {
#pragma unroll
            for (int p = 0; p < 2; p++) {
                s[n8][p] += __shfl_xor_sync(0xffffffffu, s[n8][p], o);
                q[n8][p] += __shfl_xor_sync(0xffffffffu, q[n8][p], o);
            }
        }
    }
    if (lane < 4) {
#pragma unroll
        for (int n8 = 0; n8 < 4; n8++) {
#pragma unroll
            for (int p = 0; p < 2; p++) {
                int col = warpCol + n8 * 8 + 2 * lane + p;
                atomicAdd(&g_stats[col], s[n8][p]);
                atomicAdd(&g_stats[HID + col], q[n8][p]);
            }
        }
    }
}

// ---------------- X2[par] rec-half = bf16-split of BN(rec); BN coeffs in-block ----------------
__global__ void x2_convert(int par, const float* __restrict__ gamma,
                           const float* __restrict__ beta) {
    __shared__ float sA[HID], sB[HID];
    int t = threadIdx.x;
    if (t < HID) {
        float mean = g_stats[t] * (1.0f / N_VARS);
        float var = g_stats[HID + t] * (1.0f / N_VARS) - mean * mean;
        float a = gamma[t] * rsqrtf(var + BN_EPS);
        sA[t] = a;
        sB[t] = beta[t] - mean * a;
    }
    __syncthreads();
    int idx = blockIdx.x * blockDim.x + t;
    if (idx >= NP * 16) return;
    int row = idx >> 4;
    int k = (idx & 15) * 8;
    const float* src = &g_rec[(size_t)row * HID + k];
    float4 v0 = *(const float4*)src, v1 = *(const float4*)(src + 4);
    float4 a0 = *(const float4*)&sA[k], a1 = *(const float4*)&sA[k + 4];
    float4 b0 = *(const float4*)&sB[k], b1 = *(const float4*)&sB[k + 4];
    v0.x = fmaf(v0.x, a0.x, b0.x); v0.y = fmaf(v0.y, a0.y, b0.y);
    v0.z = fmaf(v0.z, a0.z, b0.z); v0.w = fmaf(v0.w, a0.w, b0.w);
    v1.x = fmaf(v1.x, a1.x, b1.x); v1.y = fmaf(v1.y, a1.y, b1.y);
    v1.z = fmaf(v1.z, a1.z, b1.z); v1.w = fmaf(v1.w, a1.w, b1.w);
    uint4 hi, lo; split8(v0, v1, hi, lo);
    ((uint4*)g_X2h[par])[row * 32 + (idx & 15)] = hi;
    ((uint4*)g_X2l[par])[row * 32 + (idx & 15)] = lo;
}

// ---------------- gates = X2[par] @ W2^T + LSTM; split(h) -> X2[par^1] ----------------
__global__ void __launch_bounds__(512, 1)
gates_mma(float* __restrict__ hout, int par) {
    extern __shared__ char smraw[];
    uint32_t sb0 = smem_u32(smraw);
    uint32_t sb = (sb0 + 1023) & ~1023u;
    char* smp = smraw + (sb - sb0);
    const int tid = threadIdx.x;
    const int wid = tid >> 5, lane = tid & 31;
    const int rowBase = blockIdx.x * 128;
    const int by = blockIdx.y;
    const int warpRow = (wid >> 2) * 32, warpCol = (wid & 3) * 32;

    // reset BN stats for the next step (after x2_convert consumed them)
    if (blockIdx.x == 0 && by == 0 && tid < 2 * HID) g_stats[tid] = 0.f;

    float acc[2][4][4];
#pragma unroll
    for (int m = 0; m < 2; m++)
#pragma unroll
        for (int n = 0; n < 4; n++)
#pragma unroll
            for (int c = 0; c < 4; c++) acc[m][n][c] = 0.f;

    const uint4* Ah = (const uint4*)g_X2h[par];
    const uint4* Al = (const uint4*)g_X2l[par];
    const uint4* Bh = (const uint4*)g_W2h;
    const uint4* Bl = (const uint4*)g_W2l;
    const int ABASE = rowBase * 32;
    const int BBASE = by * 128 * 32;
    uint32_t st0 = sb, st1 = sb + STAGE_SZ, st2 = sb + 2 * STAGE_SZ;

    stage_tiles(st0, Ah, Al, Bh, Bl, ABASE, BBASE, 0, tid);  CP_COMMIT();
    stage_tiles(st1, Ah, Al, Bh, Bl, ABASE, BBASE, 8, tid);  CP_COMMIT();
    stage_tiles(st2, Ah, Al, Bh, Bl, ABASE, BBASE, 16, tid); CP_COMMIT();
    CP_WAIT(2); __syncthreads();
    chunk_compute2(st0 + T_A_HI, st0 + T_A_LO, st0 + T_B_HI, st0 + T_B_LO,
                   warpRow, warpCol, lane, acc);
    __syncthreads();
    stage_tiles(st0, Ah, Al, Bh, Bl, ABASE, BBASE, 24, tid); CP_COMMIT();
    CP_WAIT(2); __syncthreads();
    chunk_compute2(st1 + T_A_HI, st1 + T_A_LO, st1 + T_B_HI, st1 + T_B_LO,
                   warpRow, warpCol, lane, acc);
    CP_WAIT(1); __syncthreads();
    chunk_compute2(st2 + T_A_HI, st2 + T_A_LO, st2 + T_B_HI, st2 + T_B_LO,
                   warpRow, warpCol, lane, acc);
    CP_WAIT(0); __syncthreads();
    chunk_compute2(st0 + T_A_HI, st0 + T_A_LO, st0 + T_B_HI, st0 + T_B_LO,
                   warpRow, warpCol, lane, acc);
    __syncthreads();

    // stage gate tile to smem overlay, then fused LSTM pointwise
    float* Cs = (float*)smp;                   // 128 x 128 fp32 overlay
#pragma unroll
    for (int mt = 0; mt < 2; mt++) {
        int r0 = warpRow + mt * 16 + (lane >> 2);
#pragma unroll
        for (int n8 = 0; n8 < 4; n8++) {
            int col = warpCol + n8 * 8 + 2 * (lane & 3);
            float* c = acc[mt][n8];
            *(float2*)&Cs[r0 * 128 + col]       = make_float2(c[0], c[1]);
            *(float2*)&Cs[(r0 + 8) * 128 + col] = make_float2(c[2], c[3]);
        }
    }
    __syncthreads();
    __nv_bfloat16* X2h_w = g_X2h[par ^ 1];
    __nv_bfloat16* X2l_w = g_X2l[par ^ 1];
#pragma unroll
    for (int it = 0; it < 8; it++) {
        int cell = tid + 512 * it;
        int row = cell >> 5, jq = cell & 31;
        int grow = rowBase + row;
        int j = by * 32 + jq;
        float4 gt = *(const float4*)&Cs[row * 128 + jq * 4];   // i,f,g,o
        size_t idx = (size_t)grow * HID + j;
        float ig = gt.x + g_bias[j];
        float fg = gt.y + g_bias[HID + j];
        float gg = gt.z + g_bias[2 * HID + j];
        float og = gt.w + g_bias[3 * HID + j];
        float cn = sigf(fg) * g_c[idx] + sigf(ig) * tanhf(gg);
        g_c[idx] = cn;
        float hv = sigf(og) * tanhf(cn);
        hout[idx] = hv;
        __nv_bfloat16 hb = __float2bfloat16(hv);
        X2h_w[(size_t)grow * 256 + 128 + j] = hb;
        X2l_w[(size_t)grow * 256 + 128 + j] = __float2bfloat16(hv - __bfloat162float(hb));
    }
}

// ---------------- output: softmax(h @ W_out^T) ----------------
__global__ void out_kernel(const float* __restrict__ hin,
                           const float* __restrict__ W_out,
                           float* __restrict__ out) {
    int v = (blockIdx.x * blockDim.x + threadIdx.x) >> 5;
    int lane = threadIdx.x & 31;
    if (v >= N_VARS) return;
    float p0 = 0.f, p1 = 0.f, p2 = 0.f;
#pragma unroll
    for (int q = 0; q < 4; q++) {
        int col = lane + q * 32;
        float hv = hin[(size_t)v * HID + col];
        p0 = fmaf(hv, __ldg(&W_out[col]), p0);
        p1 = fmaf(hv, __ldg(&W_out[HID + col]), p1);
        p2 = fmaf(hv, __ldg(&W_out[2 * HID + col]), p2);
    }
#pragma unroll
    for (int o = 16; o > 0; o >>= 1) {
        p0 += __shfl_xor_sync(0xffffffffu, p0, o);
        p1 += __shfl_xor_sync(0xffffffffu, p1, o);
        p2 += __shfl_xor_sync(0xffffffffu, p2, o);
    }
    if (lane == 0) {
        float m = fmaxf(p0, fmaxf(p1, p2));
        float e0 = expf(p0 - m), e1 = expf(p1 - m), e2 = expf(p2 - m);
        float inv = 1.f / (e0 + e1 + e2);
        out[v * 3 + 0] = e0 * inv;
        out[v * 3 + 1] = e1 * inv;
        out[v * 3 + 2] = e2 * inv;
    }
}

// ---------------- launch ----------------
extern "C" void kernel_launch(void* const* d_in, const int* in_sizes, int n_in,
                              void* d_out, int out_size) {
    const float* h0      = (const float*)d_in[0];
    const float* var_reg = (const float*)d_in[1];
    const float* W_msg   = (const float*)d_in[2];
    const float* gamma   = (const float*)d_in[3];
    const float* beta    = (const float*)d_in[4];
    const float* W_ih    = (const float*)d_in[5];
    const float* W_hh    = (const float*)d_in[6];
    const float* b_ih    = (const float*)d_in[7];
    const float* b_hh    = (const float*)d_in[8];
    const float* W_out   = (const float*)d_in[9];
    const int*   ei      = (const int*)d_in[10];
    (void)in_sizes; (void)n_in;

    cudaFuncSetAttribute(gather_rec, cudaFuncAttributeMaxDynamicSharedMemorySize, SMEMSZ_R);
    cudaFuncSetAttribute(gates_mma,  cudaFuncAttributeMaxDynamicSharedMemorySize, SMEMSZ_G);

    float *hA, *hB, *cbuf, *stats;
    int *degi, *cur;
    cudaGetSymbolAddress((void**)&hA, g_hA);
    cudaGetSymbolAddress((void**)&hB, g_hB);
    cudaGetSymbolAddress((void**)&cbuf, g_c);
    cudaGetSymbolAddress((void**)&degi, g_degi);
    cudaGetSymbolAddress((void**)&cur, g_cur);
    cudaGetSymbolAddress((void**)&stats, g_stats);

    cudaStream_t s = 0;
    cudaMemcpyAsync(hA, h0, (size_t)N_VARS * HID * sizeof(float),
                    cudaMemcpyDeviceToDevice, s);
    cudaMemsetAsync(hA + (size_t)N_VARS * HID, 0,
                    (size_t)(NP - N_VARS) * HID * sizeof(float), s);
    cudaMemsetAsync(cbuf, 0, (size_t)NP * HID * sizeof(float), s);
    cudaMemsetAsync(degi, 0, (size_t)NP * sizeof(int), s);
    cudaMemsetAsync(cur, 0, (size_t)NP * sizeof(int), s);
    cudaMemsetAsync(stats, 0, 2 * HID * sizeof(float), s);

    prep_kernel<<<512, 256, 0, s>>>(W_msg, W_ih, W_hh, b_ih, b_hh);
    degcnt_kernel<<<(2 * N_EDGES + 255) / 256, 256, 0, s>>>(ei);
    scan_kernel<<<1, 1024, 0, s>>>();
    fill_kernel<<<(2 * N_EDGES + 255) / 256, 256, 0, s>>>(ei);
    h0split<<<(NP * 16 + 255) / 256, 256, 0, s>>>(hA);

    const float* hin = hA;
    float* hout = hB;
    for (int st = 0; st < STEPS; ++st) {
        int par = st & 1;
        gather_rec<<<NBLK, 512, SMEMSZ_R, s>>>(hin, var_reg);
        x2_convert<<<(NP * 16 + 255) / 256, 256, 0, s>>>(par, gamma, beta);
        gates_mma<<<dim3(NBLK, 4), 512, SMEMSZ_G, s>>>(hout, par);
        const float* tmp = hout;
        hout = (float*)hin;
        hin = tmp;
    }
    out_kernel<<<(N_VARS * 32 + 255) / 256, 256, 0, s>>>(hin, W_out, (float*)d_out);
}

// round 12
// speedup vs baseline: 1.1058x; 1.0682x over previous
#include <cuda_runtime.h>
#include <cuda_bf16.h>
#include <math.h>
#include <stdint.h>

#define N_VARS 50000
#define HID 128
#define N_EDGES 400000
#define NP 50048            // 391 * 128
#define NBLK (NP / 128)     // 391
#define STEPS 4
#define BN_EPS 1e-5f

// ---------------- static device scratch ----------------
__device__ float g_hA[NP * HID];
__device__ float g_hB[NP * HID];
__device__ float g_c[NP * HID];
__device__ float g_rec[NP * HID];
__device__ float g_degf[NP];
__device__ int   g_degi[NP];
__device__ int   g_off[NP + 1];
__device__ int   g_cur[NP];
__device__ int   g_adj[2 * N_EDGES];
__device__ __align__(16) __nv_bfloat16 g_W1h[128 * 256];   // rec weights  [n][k]
__device__ __align__(16) __nv_bfloat16 g_W1l[128 * 256];
__device__ __align__(16) __nv_bfloat16 g_W2h[512 * 256];   // gate weights [n=4j+g][k]
__device__ __align__(16) __nv_bfloat16 g_W2l[512 * 256];
__device__ __align__(16) __nv_bfloat16 g_X1h[NP * 256];    // [agg | deg*h] hi
__device__ __align__(16) __nv_bfloat16 g_X1l[NP * 256];
// ping-pong buffers: [BN(rec) | h] — gates reads par, writes h-half of par^1
__device__ __align__(16) __nv_bfloat16 g_X2h[2][NP * 256];
__device__ __align__(16) __nv_bfloat16 g_X2l[2][NP * 256];
__device__ float g_bias[4 * HID];
__device__ float g_stats[2 * HID];

__device__ __forceinline__ float sigf(float x) { return 1.0f / (1.0f + expf(-x)); }

__device__ __forceinline__ uint32_t smem_u32(const void* p) {
    uint32_t a;
    asm("{ .reg .u64 t; cvta.to.shared.u64 t, %1; cvt.u32.u64 %0, t; }" : "=r"(a) : "l"(p));
    return a;
}
#define SWZ(o) ((o) ^ (((o) >> 3) & 0x70))

#define LDSM4(R, A) \
    asm volatile("ldmatrix.sync.aligned.m8n8.x4.shared.b16 {%0,%1,%2,%3}, [%4];" \
                 : "=r"((R)[0]), "=r"((R)[1]), "=r"((R)[2]), "=r"((R)[3]) : "r"(A))

#define MMA(C, A, B0, B1) \
    asm volatile("mma.sync.aligned.m16n8k16.row.col.f32.bf16.bf16.f32 " \
                 "{%0,%1,%2,%3},{%4,%5,%6,%7},{%8,%9},{%0,%1,%2,%3};" \
                 : "+f"((C)[0]), "+f"((C)[1]), "+f"((C)[2]), "+f"((C)[3]) \
                 : "r"((A)[0]), "r"((A)[1]), "r"((A)[2]), "r"((A)[3]), "r"(B0), "r"(B1))

#define CP16(dst_u32, src_ptr) \
    asm volatile("cp.async.cg.shared.global [%0], [%1], 16;" \
                 :: "r"(dst_u32), "l"(src_ptr))
#define CP_COMMIT() asm volatile("cp.async.commit_group;")
#define CP_WAIT(n)  asm volatile("cp.async.wait_group %0;" :: "n"(n))

union Pack8 { __nv_bfloat16 b[8]; uint4 u; };
__device__ __forceinline__ void split8(float4 a, float4 b, uint4& hi, uint4& lo) {
    float v[8] = {a.x, a.y, a.z, a.w, b.x, b.y, b.z, b.w};
    Pack8 ph, pl;
#pragma unroll
    for (int i = 0; i < 8; i++) {
        __nv_bfloat16 h = __float2bfloat16(v[i]);
        ph.b[i] = h;
        pl.b[i] = __float2bfloat16(v[i] - __bfloat162float(h));
    }
    hi = ph.u; lo = pl.u;
}
union Pack4 { __nv_bfloat16 b[4]; uint2 u; };
__device__ __forceinline__ void split4(float4 a, uint2& hi, uint2& lo) {
    float v[4] = {a.x, a.y, a.z, a.w};
    Pack4 ph, pl;
#pragma unroll
    for (int i = 0; i < 4; i++) {
        __nv_bfloat16 h = __float2bfloat16(v[i]);
        ph.b[i] = h;
        pl.b[i] = __float2bfloat16(v[i] - __bfloat162float(h));
    }
    hi = ph.u; lo = pl.u;
}

// smem: 3 stages x (A_hi, A_lo, B_hi, B_lo), each tile 128x64 bf16 = 16KB
#define T_A_HI 0
#define T_A_LO 16384
#define T_B_HI 32768
#define T_B_LO 49152
#define STAGE_SZ 65536
#define SMEMSZ (1024 + 3 * STAGE_SZ)

// ---------------- prep: bf16-split weights, fused bias ----------------
__global__ void prep_kernel(const float* __restrict__ W_msg,
                            const float* __restrict__ W_ih,
                            const float* __restrict__ W_hh,
                            const float* __restrict__ b_ih,
                            const float* __restrict__ b_hh) {
    int t = blockIdx.x * blockDim.x + threadIdx.x;
    int stride = gridDim.x * blockDim.x;
    for (int i = t; i < 128 * 256; i += stride) {
        float w = W_msg[i];
        __nv_bfloat16 h = __float2bfloat16(w);
        g_W1h[i] = h;
        g_W1l[i] = __float2bfloat16(w - __bfloat162float(h));
    }
    for (int i = t; i < 512 * 256; i += stride) {
        int n = i >> 8, k = i & 255;
        int j = n >> 2, g = n & 3;
        int wrow = g * HID + j;
        float w = (k < HID) ? W_ih[wrow * HID + k] : W_hh[wrow * HID + (k - HID)];
        __nv_bfloat16 h = __float2bfloat16(w);
        g_W2h[i] = h;
        g_W2l[i] = __float2bfloat16(w - __bfloat162float(h));
    }
    for (int i = t; i < 4 * HID; i += stride) g_bias[i] = b_ih[i] + b_hh[i];
}

// ---------------- CSR build ----------------
__global__ void degcnt_kernel(const int* __restrict__ ei) {
    int i = blockIdx.x * blockDim.x + threadIdx.x;
    if (i < 2 * N_EDGES) atomicAdd(&g_degi[ei[i]], 1);
}

__global__ void scan_kernel() {       // single block, 1024 threads
    __shared__ int part[1024];
    int t = threadIdx.x;
    const int CH = (N_VARS + 1023) / 1024;
    int base = t * CH;
    int s = 0;
    for (int i = 0; i < CH; i++) {
        int idx = base + i;
        if (idx < N_VARS) s += g_degi[idx];
    }
    part[t] = s;
    __syncthreads();
    int val = s;
#pragma unroll
    for (int d = 1; d < 1024; d <<= 1) {
        int v = (t >= d) ? part[t - d] : 0;
        __syncthreads();
        part[t] += v;
        __syncthreads();
    }
    int excl = part[t] - val;
    int run = excl;
    for (int i = 0; i < CH; i++) {
        int idx = base + i;
        if (idx < N_VARS) {
            g_off[idx] = run;
            int d = g_degi[idx];
            g_degf[idx] = (float)d;
            run += d;
        }
    }
    if (t == 1023) g_off[N_VARS] = run;
}

__global__ void fill_kernel(const int* __restrict__ ei) {
    int i = blockIdx.x * blockDim.x + threadIdx.x;
    if (i >= 2 * N_EDGES) return;
    int s, d;
    if (i < N_EDGES) { s = ei[i]; d = ei[N_EDGES + i]; }
    else             { s = ei[i]; d = ei[i - N_EDGES]; }
    int pos = atomicAdd(&g_cur[d], 1);
    g_adj[g_off[d] + pos] = s;
}

// ---------------- h0 split -> X2[0] h-part (once) ----------------
__global__ void h0split(const float* __restrict__ hin) {
    int idx = blockIdx.x * blockDim.x + threadIdx.x;
    if (idx >= NP * 16) return;
    int row = idx >> 4, i = idx & 15;
    const float* src = &hin[(size_t)row * HID + i * 8];
    float4 v0 = *(const float4*)src, v1 = *(const float4*)(src + 4);
    uint4 hi, lo; split8(v0, v1, hi, lo);
    ((uint4*)g_X2h[0])[row * 32 + 16 + i] = hi;
    ((uint4*)g_X2l[0])[row * 32 + 16 + i] = lo;
}

// ---------------- CSR gather -> X1 = split([agg | deg*h]) ----------------
__global__ void gather_kernel(const float* __restrict__ hin) {
    int w = (blockIdx.x * blockDim.x + threadIdx.x) >> 5;
    int lane = threadIdx.x & 31;
    if (w >= N_VARS) return;
    int e = g_off[w], end = g_off[w + 1];
    int c4 = lane * 4;
    float4 s0 = make_float4(0, 0, 0, 0), s1 = make_float4(0, 0, 0, 0);
    float4 s2 = make_float4(0, 0, 0, 0), s3 = make_float4(0, 0, 0, 0);
    for (; e + 4 <= end; e += 4) {
        int u0 = g_adj[e], u1 = g_adj[e + 1], u2 = g_adj[e + 2], u3 = g_adj[e + 3];
        float4 a = *(const float4*)&hin[(size_t)u0 * HID + c4];
        float4 b = *(const float4*)&hin[(size_t)u1 * HID + c4];
        float4 c = *(const float4*)&hin[(size_t)u2 * HID + c4];
        float4 d = *(const float4*)&hin[(size_t)u3 * HID + c4];
        s0.x += a.x; s0.y += a.y; s0.z += a.z; s0.w += a.w;
        s1.x += b.x; s1.y += b.y; s1.z += b.z; s1.w += b.w;
        s2.x += c.x; s2.y += c.y; s2.z += c.z; s2.w += c.w;
        s3.x += d.x; s3.y += d.y; s3.z += d.z; s3.w += d.w;
    }
    for (; e < end; e++) {
        int u = g_adj[e];
        float4 a = *(const float4*)&hin[(size_t)u * HID + c4];
        s0.x += a.x; s0.y += a.y; s0.z += a.z; s0.w += a.w;
    }
    s0.x += s1.x + s2.x + s3.x; s0.y += s1.y + s2.y + s3.y;
    s0.z += s1.z + s2.z + s3.z; s0.w += s1.w + s2.w + s3.w;
    uint2 hi, lo;
    split4(s0, hi, lo);
    ((uint2*)g_X1h)[w * 64 + lane] = hi;        // k = c4
    ((uint2*)g_X1l)[w * 64 + lane] = lo;
    // deg * h part
    float d = g_degf[w];
    float4 hv = *(const float4*)&hin[(size_t)w * HID + c4];
    hv.x *= d; hv.y *= d; hv.z *= d; hv.w *= d;
    split4(hv, hi, lo);
    ((uint2*)g_X1h)[w * 64 + 32 + lane] = hi;   // k = 128 + c4
    ((uint2*)g_X1l)[w * 64 + 32 + lane] = lo;
}

// ---------------- cp.async tile staging ----------------
__device__ __forceinline__ void stage_tiles(uint32_t sbase,
                                            const uint4* __restrict__ Ah,
                                            const uint4* __restrict__ Al,
                                            const uint4* __restrict__ Bh,
                                            const uint4* __restrict__ Bl,
                                            int aBase32, int bBase32, int k8, int tid) {
#pragma unroll
    for (int idx = tid; idx < 1024; idx += 512) {
        int row = idx >> 3, i = idx & 7;
        uint32_t sw = SWZ((uint32_t)(row * 128 + i * 16));
        int ga = aBase32 + row * 32 + k8 + i;
        int gb = bBase32 + row * 32 + k8 + i;
        CP16(sbase + T_A_HI + sw, Ah + ga);
        CP16(sbase + T_A_LO + sw, Al + ga);
        CP16(sbase + T_B_HI + sw, Bh + gb);
        CP16(sbase + T_B_LO + sw, Bl + gb);
    }
}

// ---------------- warp-tile compute core (one K-chunk of 64), 32x32 warp tile ----------------
__device__ __forceinline__ void chunk_compute(uint32_t sb, int warpRow, int warpCol,
                                              int lane, float acc[2][4][4]) {
#pragma unroll
    for (int ks = 0; ks < 4; ks++) {
        uint32_t aH[2][4], aL[2][4];
#pragma unroll
        for (int mt = 0; mt < 2; mt++) {
            uint32_t off = (uint32_t)((warpRow + mt * 16 + (lane & 15)) * 128
                                      + ks * 32 + ((lane >> 4) & 1) * 16);
            uint32_t sw = SWZ(off);
            LDSM4(aH[mt], sb + T_A_HI + sw);
            LDSM4(aL[mt], sb + T_A_LO + sw);
        }
#pragma unroll
        for (int np = 0; np < 2; np++) {
            uint32_t bH[4], bL[4];
            uint32_t off = (uint32_t)((warpCol + np * 16 + ((lane >> 4) & 1) * 8 + (lane & 7)) * 128
                                      + ks * 32 + ((lane >> 3) & 1) * 16);
            uint32_t sw = SWZ(off);
            LDSM4(bH, sb + T_B_HI + sw);
            LDSM4(bL, sb + T_B_LO + sw);
#pragma unroll
            for (int mt = 0; mt < 2; mt++) {
#pragma unroll
                for (int nt = 0; nt < 2; nt++) {
                    float* c = acc[mt][np * 2 + nt];
                    MMA(c, aH[mt], bH[nt * 2], bH[nt * 2 + 1]);
                    MMA(c, aH[mt], bL[nt * 2], bL[nt * 2 + 1]);
                    MMA(c, aL[mt], bH[nt * 2], bH[nt * 2 + 1]);
                }
            }
        }
    }
}

// ---------------- shared GEMM pipeline: 3-stage, K chunks of 64 ----------------
#define GEMM_PIPELINE(Ah, Al, Bh, Bl, ABASE, BBASE)                                    \
    stage_tiles(sb,                Ah, Al, Bh, Bl, ABASE, BBASE,  0, tid); CP_COMMIT();\
    stage_tiles(sb + STAGE_SZ,     Ah, Al, Bh, Bl, ABASE, BBASE,  8, tid); CP_COMMIT();\
    stage_tiles(sb + 2 * STAGE_SZ, Ah, Al, Bh, Bl, ABASE, BBASE, 16, tid); CP_COMMIT();\
    CP_WAIT(2); __syncthreads();                                                       \
    chunk_compute(sb, warpRow, warpCol, lane, acc);                                    \
    __syncthreads();                                                                   \
    stage_tiles(sb, Ah, Al, Bh, Bl, ABASE, BBASE, 24, tid); CP_COMMIT();               \
    CP_WAIT(2); __syncthreads();                                                       \
    chunk_compute(sb + STAGE_SZ, warpRow, warpCol, lane, acc);                         \
    CP_WAIT(1); __syncthreads();                                                       \
    chunk_compute(sb + 2 * STAGE_SZ, warpRow, warpCol, lane, acc);                     \
    CP_WAIT(0); __syncthreads();                                                       \
    chunk_compute(sb, warpRow, warpCol, lane, acc);                                    \
    __syncthreads();

// ---------------- rec = (X1 @ W1^T) * var_reg, with fused BN stats ----------------
__global__ void __launch_bounds__(512, 1)
rec_mma(const float* __restrict__ var_reg) {
    extern __shared__ char smraw[];
    uint32_t sb0 = smem_u32(smraw);
    uint32_t sb = (sb0 + 1023) & ~1023u;
    const int tid = threadIdx.x;
    const int wid = tid >> 5, lane = tid & 31;
    const int rowBase = blockIdx.x * 128;
    const int warpRow = (wid >> 2) * 32, warpCol = (wid & 3) * 32;

    float acc[2][4][4];
#pragma unroll
    for (int m = 0; m < 2; m++)
#pragma unroll
        for (int n = 0; n < 4; n++)
#pragma unroll
            for (int c = 0; c < 4; c++) acc[m][n][c] = 0.f;

    GEMM_PIPELINE((const uint4*)g_X1h, (const uint4*)g_X1l,
                  (const uint4*)g_W1h, (const uint4*)g_W1l,
                  rowBase * 32, 0)

    // epilogue: scale by var_reg, store rec, fused column stats
    float s[4][2] = {}, q[4][2] = {};
#pragma unroll
    for (int mt = 0; mt < 2; mt++) {
        int r0 = rowBase + warpRow + mt * 16 + (lane >> 2);
        int r1 = r0 + 8;
        float vr0 = (r0 < N_VARS) ? var_reg[r0] : 0.f;
        float vr1 = (r1 < N_VARS) ? var_reg[r1] : 0.f;
#pragma unroll
        for (int n8 = 0; n8 < 4; n8++) {
            int col = warpCol + n8 * 8 + 2 * (lane & 3);
            float* c = acc[mt][n8];
            float v00 = c[0] * vr0, v01 = c[1] * vr0;
            float v10 = c[2] * vr1, v11 = c[3] * vr1;
            *(float2*)&g_rec[(size_t)r0 * HID + col] = make_float2(v00, v01);
            *(float2*)&g_rec[(size_t)r1 * HID + col] = make_float2(v10, v11);
            s[n8][0] += v00 + v10;  q[n8][0] += v00 * v00 + v10 * v10;
            s[n8][1] += v01 + v11;  q[n8][1] += v01 * v01 + v11 * v11;
        }
    }
#pragma unroll
    for (int o = 4; o <= 16; o <<= 1) {
#pragma unroll
        for (int n8 = 0; n8 < 4; n8++) {
#pragma unroll
            for (int p = 0; p < 2; p++) {
                s[n8][p] += __shfl_xor_sync(0xffffffffu, s[n8][p], o);
                q[n8][p] += __shfl_xor_sync(0xffffffffu, q[n8][p], o);
            }
        }
    }
    if (lane < 4) {
#pragma unroll
        for (int n8 = 0; n8 < 4; n8++) {
#pragma unroll
            for (int p = 0; p < 2; p++) {
                int col = warpCol + n8 * 8 + 2 * lane + p;
                atomicAdd(&g_stats[col], s[n8][p]);
                atomicAdd(&g_stats[HID + col], q[n8][p]);
            }
        }
    }
}

// ---------------- X2[par] rec-half = bf16-split of BN(rec); BN coeffs in-block ----------------
__global__ void x2_convert(int par, const float* __restrict__ gamma,
                           const float* __restrict__ beta) {
    __shared__ float sA[HID], sB[HID];
    int t = threadIdx.x;
    if (t < HID) {
        float mean = g_stats[t] * (1.0f / N_VARS);
        float var = g_stats[HID + t] * (1.0f / N_VARS) - mean * mean;
        float a = gamma[t] * rsqrtf(var + BN_EPS);
        sA[t] = a;
        sB[t] = beta[t] - mean * a;
    }
    __syncthreads();
    int idx = blockIdx.x * blockDim.x + t;
    if (idx >= NP * 16) return;
    int row = idx >> 4;
    int k = (idx & 15) * 8;
    const float* src = &g_rec[(size_t)row * HID + k];
    float4 v0 = *(const float4*)src, v1 = *(const float4*)(src + 4);
    float4 a0 = *(const float4*)&sA[k], a1 = *(const float4*)&sA[k + 4];
    float4 b0 = *(const float4*)&sB[k], b1 = *(const float4*)&sB[k + 4];
    v0.x = fmaf(v0.x, a0.x, b0.x); v0.y = fmaf(v0.y, a0.y, b0.y);
    v0.z = fmaf(v0.z, a0.z, b0.z); v0.w = fmaf(v0.w, a0.w, b0.w);
    v1.x = fmaf(v1.x, a1.x, b1.x); v1.y = fmaf(v1.y, a1.y, b1.y);
    v1.z = fmaf(v1.z, a1.z, b1.z); v1.w = fmaf(v1.w, a1.w, b1.w);
    uint4 hi, lo; split8(v0, v1, hi, lo);
    ((uint4*)g_X2h[par])[row * 32 + (idx & 15)] = hi;
    ((uint4*)g_X2l[par])[row * 32 + (idx & 15)] = lo;
}

// ---------------- gates = X2[par] @ W2^T + LSTM pointwise; split(h) -> X2[par^1] ----------------
// grid = dim3(4, NBLK): by = blockIdx.x so the 4 CTAs sharing an A-slab run adjacently
__global__ void __launch_bounds__(512, 1)
gates_mma(float* __restrict__ hout, int par) {
    extern __shared__ char smraw[];
    uint32_t sb0 = smem_u32(smraw);
    uint32_t sb = (sb0 + 1023) & ~1023u;
    char* smp = smraw + (sb - sb0);
    const int tid = threadIdx.x;
    const int wid = tid >> 5, lane = tid & 31;
    const int by = blockIdx.x;                 // 0..3 — fast dimension
    const int bx = blockIdx.y;                 // row block — slow dimension
    const int rowBase = bx * 128;
    const int warpRow = (wid >> 2) * 32, warpCol = (wid & 3) * 32;

    // reset BN stats for the next step (after x2_convert consumed them)
    if (bx == 0 && by == 0 && tid < 2 * HID) g_stats[tid] = 0.f;

    float acc[2][4][4];
#pragma unroll
    for (int m = 0; m < 2; m++)
#pragma unroll
        for (int n = 0; n < 4; n++)
#pragma unroll
            for (int c = 0; c < 4; c++) acc[m][n][c] = 0.f;

    GEMM_PIPELINE((const uint4*)g_X2h[par], (const uint4*)g_X2l[par],
                  (const uint4*)g_W2h, (const uint4*)g_W2l,
                  rowBase * 32, by * 128 * 32)

    // stage gate tile to smem overlay, then fused LSTM pointwise
    float* Cs = (float*)smp;                   // 128 x 128 fp32 overlay (stage 0)
#pragma unroll
    for (int mt = 0; mt < 2; mt++) {
        int r0 = warpRow + mt * 16 + (lane >> 2);
#pragma unroll
        for (int n8 = 0; n8 < 4; n8++) {
            int col = warpCol + n8 * 8 + 2 * (lane & 3);
            float* c = acc[mt][n8];
            *(float2*)&Cs[r0 * 128 + col]       = make_float2(c[0], c[1]);
            *(float2*)&Cs[(r0 + 8) * 128 + col] = make_float2(c[2], c[3]);
        }
    }
    __syncthreads();
    __nv_bfloat16* X2h_w = g_X2h[par ^ 1];
    __nv_bfloat16* X2l_w = g_X2l[par ^ 1];
#pragma unroll
    for (int it = 0; it < 8; it++) {
        int cell = tid + 512 * it;
        int row = cell >> 5, jq = cell & 31;
        int grow = rowBase + row;
        int j = by * 32 + jq;
        float4 gt = *(const float4*)&Cs[row * 128 + jq * 4];   // i,f,g,o
        size_t idx = (size_t)grow * HID + j;
        float ig = gt.x + g_bias[j];
        float fg = gt.y + g_bias[HID + j];
        float gg = gt.z + g_bias[2 * HID + j];
        float og = gt.w + g_bias[3 * HID + j];
        float cn = sigf(fg) * g_c[idx] + sigf(ig) * tanhf(gg);
        g_c[idx] = cn;
        float hv = sigf(og) * tanhf(cn);
        hout[idx] = hv;
        __nv_bfloat16 hb = __float2bfloat16(hv);
        X2h_w[(size_t)grow * 256 + 128 + j] = hb;
        X2l_w[(size_t)grow * 256 + 128 + j] = __float2bfloat16(hv - __bfloat162float(hb));
    }
}

// ---------------- output: softmax(h @ W_out^T) ----------------
__global__ void out_kernel(const float* __restrict__ hin,
                           const float* __restrict__ W_out,
                           float* __restrict__ out) {
    int v = (blockIdx.x * blockDim.x + threadIdx.x) >> 5;
    int lane = threadIdx.x & 31;
    if (v >= N_VARS) return;
    float p0 = 0.f, p1 = 0.f, p2 = 0.f;
#pragma unroll
    for (int q = 0; q < 4; q++) {
        int col = lane + q * 32;
        float hv = hin[(size_t)v * HID + col];
        p0 = fmaf(hv, __ldg(&W_out[col]), p0);
        p1 = fmaf(hv, __ldg(&W_out[HID + col]), p1);
        p2 = fmaf(hv, __ldg(&W_out[2 * HID + col]), p2);
    }
#pragma unroll
    for (int o = 16; o > 0; o >>= 1) {
        p0 += __shfl_xor_sync(0xffffffffu, p0, o);
        p1 += __shfl_xor_sync(0xffffffffu, p1, o);
        p2 += __shfl_xor_sync(0xffffffffu, p2, o);
    }
    if (lane == 0) {
        float m = fmaxf(p0, fmaxf(p1, p2));
        float e0 = expf(p0 - m), e1 = expf(p1 - m), e2 = expf(p2 - m);
        float inv = 1.f / (e0 + e1 + e2);
        out[v * 3 + 0] = e0 * inv;
        out[v * 3 + 1] = e1 * inv;
        out[v * 3 + 2] = e2 * inv;
    }
}

// ---------------- launch ----------------
extern "C" void kernel_launch(void* const* d_in, const int* in_sizes, int n_in,
                              void* d_out, int out_size) {
    const float* h0      = (const float*)d_in[0];
    const float* var_reg = (const float*)d_in[1];
    const float* W_msg   = (const float*)d_in[2];
    const float* gamma   = (const float*)d_in[3];
    const float* beta    = (const float*)d_in[4];
    const float* W_ih    = (const float*)d_in[5];
    const float* W_hh    = (const float*)d_in[6];
    const float* b_ih    = (const float*)d_in[7];
    const float* b_hh    = (const float*)d_in[8];
    const float* W_out   = (const float*)d_in[9];
    const int*   ei      = (const int*)d_in[10];
    (void)in_sizes; (void)n_in;

    cudaFuncSetAttribute(rec_mma,   cudaFuncAttributeMaxDynamicSharedMemorySize, SMEMSZ);
    cudaFuncSetAttribute(gates_mma, cudaFuncAttributeMaxDynamicSharedMemorySize, SMEMSZ);

    float *hA, *hB, *cbuf, *stats;
    int *degi, *cur;
    cudaGetSymbolAddress((void**)&hA, g_hA);
    cudaGetSymbolAddress((void**)&hB, g_hB);
    cudaGetSymbolAddress((void**)&cbuf, g_c);
    cudaGetSymbolAddress((void**)&degi, g_degi);
    cudaGetSymbolAddress((void**)&cur, g_cur);
    cudaGetSymbolAddress((void**)&stats, g_stats);

    cudaStream_t s = 0;
    cudaMemcpyAsync(hA, h0, (size_t)N_VARS * HID * sizeof(float),
                    cudaMemcpyDeviceToDevice, s);
    cudaMemsetAsync(hA + (size_t)N_VARS * HID, 0,
                    (size_t)(NP - N_VARS) * HID * sizeof(float), s);
    cudaMemsetAsync(cbuf, 0, (size_t)NP * HID * sizeof(float), s);
    cudaMemsetAsync(degi, 0, (size_t)NP * sizeof(int), s);
    cudaMemsetAsync(cur, 0, (size_t)NP * sizeof(int), s);
    cudaMemsetAsync(stats, 0, 2 * HID * sizeof(float), s);

    prep_kernel<<<512, 256, 0, s>>>(W_msg, W_ih, W_hh, b_ih, b_hh);
    degcnt_kernel<<<(2 * N_EDGES + 255) / 256, 256, 0, s>>>(ei);
    scan_kernel<<<1, 1024, 0, s>>>();
    fill_kernel<<<(2 * N_EDGES + 255) / 256, 256, 0, s>>>(ei);
    h0split<<<(NP * 16 + 255) / 256, 256, 0, s>>>(hA);

    const float* hin = hA;
    float* hout = hB;
    for (int st = 0; st < STEPS; ++st) {
        int par = st & 1;
        gather_kernel<<<(N_VARS * 32 + 255) / 256, 256, 0, s>>>(hin);
        rec_mma<<<NBLK, 512, SMEMSZ, s>>>(var_reg);
        x2_convert<<<(NP * 16 + 255) / 256, 256, 0, s>>>(par, gamma, beta);
        gates_mma<<<dim3(4, NBLK), 512, SMEMSZ, s>>>(hout, par);
        const float* tmp = hout;
        hout = (float*)hin;
        hin = tmp;
    }
    out_kernel<<<(N_VARS * 32 + 255) / 256, 256, 0, s>>>(hin, W_out, (float*)d_out);
}